// round 13
// baseline (speedup 1.0000x reference)
#include <cuda_runtime.h>
#include <math.h>

#define TWO_PI_F 6.28318530717958647692f
#define PI_F     3.14159265358979323846f
#define INV_PI_F 0.31830988618367094f

#define PSZ   8
#define HH    64
#define WW    64
#define HPN   57
#define NPP   (HPN*HPN)        // 3249
#define NBATCH 2
#define NPTOT (NBATCH*NPP)     // 6498
#define NV    31
#define CINN  32
#define NPIX  (HH*WW)          // 4096
#define NSTAT 8192

// ---------------- device scratch ----------------
__device__ float  g_y[NBATCH*3*NPIX];
__device__ float4 g_xr4[NBATCH*NPIX];
__device__ float  g_smoothed[NBATCH*3*NPIX];
__device__ float  g_gb[NBATCH*NPIX];
__device__ float2 g_cpart[NBATCH*3*16];

// ---------------- packed f32x2 helpers ----------------
typedef unsigned long long f2;
__device__ __forceinline__ f2 pk(float lo, float hi) {
    f2 r; asm("mov.b64 %0,{%1,%2};" : "=l"(r) : "f"(lo), "f"(hi)); return r;
}
__device__ __forceinline__ f2 pk2(float c) { return pk(c, c); }
__device__ __forceinline__ void upk(f2 v, float& lo, float& hi) {
    asm("mov.b64 {%0,%1},%2;" : "=f"(lo), "=f"(hi) : "l"(v));
}
__device__ __forceinline__ f2 fma2(f2 a, f2 b, f2 c) {
    f2 r; asm("fma.rn.f32x2 %0,%1,%2,%3;" : "=l"(r) : "l"(a), "l"(b), "l"(c)); return r;
}
__device__ __forceinline__ f2 mul2(f2 a, f2 b) {
    f2 r; asm("mul.rn.f32x2 %0,%1,%2;" : "=l"(r) : "l"(a), "l"(b)); return r;
}

// ---------------- helpers ----------------
__device__ __forceinline__ float frcp(float x) {
    float r; asm("rcp.approx.f32 %0, %1;" : "=f"(r) : "f"(x)); return r;
}
__device__ __forceinline__ float wrap2pi(float v) {
    v = (v >= TWO_PI_F) ? v - TWO_PI_F : v;
    v = (v < 0.0f) ? v + TWO_PI_F : v;
    return v;
}
__device__ __forceinline__ float pow35(float u) {
    float u2 = u*u, u4 = u2*u2, u8 = u4*u4, u16 = u8*u8;
    return u16*u16*u2*u;
}
__device__ __forceinline__ float silu(float v) {
    return v / (1.0f + expf(-v));
}

// Paired h = 0.5 + atan(x)/pi (x pre-scaled by 1/eta=100).
// Polynomial section in packed f32x2; per-lane bit-identical to the proven
// R10 deg-9 scalar poly (1/pi folded). err(h) ~ 3e-6.
__device__ __forceinline__ void fast_hs2(float xa, float xb,
                                         f2 C4, f2 C3, f2 C2, f2 C1, f2 C0,
                                         float& ha, float& hb) {
    float ia = frcp(xa);
    float ib = frcp(xb);
    bool ba = fabsf(xa) > 1.0f;
    bool bb = fabsf(xb) > 1.0f;
    float ta = ba ? ia : xa;
    float tb = bb ? ib : xb;
    f2 t = pk(ta, tb);
    f2 s = mul2(t, t);
    f2 p = fma2(C4, s, C3);
    p = fma2(p, s, C2);
    p = fma2(p, s, C1);
    p = fma2(p, s, C0);
    f2 r0 = mul2(t, p);
    float ra, rb; upk(r0, ra, rb);
    float fa = ba ? (copysignf(0.5f, xa) - ra) : ra;
    float fb = bb ? (copysignf(0.5f, xb) - rb) : rb;
    ha = fa + 0.5f;
    hb = fb + 0.5f;
}

// Candidate: 1/eta folded, SIGN-FREE line coefficients (sg handled by
// predicate min/max):  M1 = 100*line(a1), M3 = -100*line(a3)
//   d13s = (sg13>0 ? min(M1,M3) : max(M1,M3)) + off13s   [exact identity]
struct Cand {
    float A1x,A1y,A3x,A3y,A4x,A4y,A2x,A2y;
    float C1,C3,C4,C2;
    float off13s, off42s;
    float y0;
    bool  min13, min42;
};

__device__ __forceinline__ Cand make_cand(const float cp[5]) {
    Cand K;
    float x0 = cp[3]; K.y0 = cp[4];
    float m0 = wrap2pi(cp[0]), m1 = wrap2pi(cp[1]), m2 = wrap2pi(cp[2]);
    float lo = fminf(m0, m1), hi = fmaxf(m0, m1);
    float a1 = fminf(lo, m2);
    float a3 = fmaxf(hi, m2);
    float a2 = fmaxf(lo, fminf(hi, m2));
    float a4 = 0.5f*(a1 + a3) + ((a3 > a1) ? PI_F : 0.0f);
    float d13 = a3 - a1;
    float m   = a2 - a4;
    float d42 = (m < 0.0f) ? m + TWO_PI_F : m;
    K.min13 = (d13 < PI_F);
    K.min42 = (d42 < PI_F);
    K.off13s = 10.0f * pow35(d13 * INV_PI_F - 1.0f);
    K.off42s = 10.0f * pow35(d42 * INV_PI_F - 1.0f);
    float s1,c1,s2,c2,s3,c3,s4,c4;
    __sincosf(a1, &s1, &c1);
    __sincosf(a2, &s2, &c2);
    __sincosf(a3, &s3, &c3);
    __sincosf(a4, &s4, &c4);
    const float f = 100.0f;
    K.A1x = -f * s1;  K.A1y =  f * c1;
    K.A3x =  f * s3;  K.A3y = -f * c3;
    K.A4x = -f * s4;  K.A4y =  f * c4;
    K.A2x =  f * s2;  K.A2y = -f * c2;
    K.C1 = -K.A1x * x0; K.C3 = -K.A3x * x0;
    K.C4 = -K.A4x * x0; K.C2 = -K.A2x * x0;
    return K;
}

__device__ __forceinline__ float cand_range(int ip, int q) {
    return (ip < 3) ? (float)q * (TWO_PI_F / 31.0f)
                    : (-3.0f + (float)q * 0.2f);
}

// ---------------- kernels ----------------
__global__ void k_conv(const float* __restrict__ x, const float* __restrict__ rw) {
    int gt = blockIdx.x * 256 + threadIdx.x;   // 0..24575
    g_smoothed[gt] = 0.0f;
    if (gt < NBATCH*NPIX) g_gb[gt] = 0.0f;

    int bo = blockIdx.x >> 4;
    int chunk = blockIdx.x & 15;
    int b = bo / 3, o = bo % 3;
    int pix = chunk * 256 + threadIdx.x;
    const float* xp = x + (size_t)b * CINN * NPIX + pix;
    float acc = 0.0f;
    #pragma unroll
    for (int c = 0; c < CINN; c++)
        acc = fmaf(xp[c * NPIX], rw[o * CINN + c], acc);
    g_y[(b*3 + o) * NPIX + pix] = acc;

    __shared__ float s1[256], s2[256];
    s1[threadIdx.x] = acc; s2[threadIdx.x] = acc * acc;
    __syncthreads();
    for (int s = 128; s > 0; s >>= 1) {
        if (threadIdx.x < s) { s1[threadIdx.x] += s1[threadIdx.x+s]; s2[threadIdx.x] += s2[threadIdx.x+s]; }
        __syncthreads();
    }
    if (threadIdx.x == 0) g_cpart[blockIdx.x] = make_float2(s1[0], s2[0]);
}

__global__ void k_bnsilu(const float* __restrict__ gamma, const float* __restrict__ beta) {
    int t = blockIdx.x * 256 + threadIdx.x;
    int b = t >> 12, pix = t & (NPIX - 1);
    float v[3];
    #pragma unroll
    for (int c = 0; c < 3; c++) {
        float s = 0.0f, ss = 0.0f;
        #pragma unroll
        for (int b2 = 0; b2 < NBATCH; b2++)
            #pragma unroll
            for (int ch = 0; ch < 16; ch++) {
                float2 pv = g_cpart[(b2*3 + c) * 16 + ch];
                s += pv.x; ss += pv.y;
            }
        float m   = s  * (1.0f / NSTAT);
        float var = ss * (1.0f / NSTAT) - m * m;
        float y   = g_y[(b*3 + c) * NPIX + pix];
        float n   = gamma[c] * (y - m) * rsqrtf(var + 1e-5f) + beta[c];
        v[c] = silu(n);
    }
    g_xr4[t] = make_float4(v[0], v[1], v[2], 0.0f);
}

// Fused: per-patch channel sums + 5-step coordinate descent + finalize.
__global__ void __launch_bounds__(64, 16) k_opt() {
    int tid  = threadIdx.x;
    int wid  = tid >> 5;
    int lane = tid & 31;
    int P = blockIdx.x;
    int b = P / NPP, pp = P - b * NPP;
    int hp = pp / HPN, wpx = pp - hp * HPN;
    const float4* tile = g_xr4 + b * NPIX + hp * WW + wpx;

    __shared__ float sAcc[2][2][11][32];  // [parity][warp][acc][lane]
    __shared__ float sRed[2][8];

    const f2 PC4 = pk2( 0.00663216f);
    const f2 PC3 = pk2(-0.02709664f);
    const f2 PC2 = pk2( 0.05733850f);
    const f2 PC1 = pk2(-0.10513345f);
    const f2 PC0 = pk2( 0.31826723f);

    // ---------- prologue: per-patch channel sums (thread = pixel) ----------
    int fxr = tid >> 3, fyc = tid & 7;
    {
        float4 fimg = __ldg(tile + fxr * WW + fyc);
        float t0 = fimg.x, t1 = fimg.y, t2 = fimg.z;
        #pragma unroll
        for (int off = 16; off > 0; off >>= 1) {
            t0 += __shfl_down_sync(0xffffffffu, t0, off);
            t1 += __shfl_down_sync(0xffffffffu, t1, off);
            t2 += __shfl_down_sync(0xffffffffu, t2, off);
        }
        if (lane == 0) { sRed[wid][0] = t0; sRed[wid][1] = t1; sRed[wid][2] = t2; }
    }
    __syncthreads();
    float4 S = make_float4(sRed[0][0] + sRed[1][0],
                           sRed[0][1] + sRed[1][1],
                           sRed[0][2] + sRed[1][2], 0.0f);

    float p[5] = {0.f, 0.f, 0.f, 0.f, 0.f};
    int q = (lane < NV) ? lane : (NV - 1);

    #pragma unroll 1
    for (int ip = 0; ip < 5; ip++) {
        float cp[5];
        #pragma unroll
        for (int j = 0; j < 5; j++) cp[j] = p[j];
        cp[ip] += cand_range(ip, q);

        Cand K = make_cand(cp);

        float acc[11];
        #pragma unroll
        for (int s = 0; s < 11; s++) acc[s] = 0.0f;

        int rbase = wid * 4;
        #pragma unroll 1
        for (int xr = 0; xr < 4; xr++) {
            int row_i = rbase + xr;
            float dy = (-1.0f + (float)row_i * (2.0f/7.0f)) - K.y0;
            float T1 = fmaf(K.A1y, dy, K.C1);
            float T3 = fmaf(K.A3y, dy, K.C3);
            float T4 = fmaf(K.A4y, dy, K.C4);
            float T2 = fmaf(K.A2y, dy, K.C2);
            const float4* row = tile + row_i * WW;
            #pragma unroll
            for (int yc = 0; yc < PSZ; yc++) {
                float cc = -1.0f + (float)yc * (2.0f/7.0f);
                float l1 = fmaf(K.A1x, cc, T1);
                float l3 = fmaf(K.A3x, cc, T3);
                float l4 = fmaf(K.A4x, cc, T4);
                float l2 = fmaf(K.A2x, cc, T2);
                float m13 = K.min13 ? fminf(l1, l3) : fmaxf(l1, l3);
                float m42 = K.min42 ? fminf(l4, l2) : fmaxf(l4, l2);
                float d13s = m13 + K.off13s;
                float d42s = m42 + K.off42s;
                float u, h1;
                fast_hs2(d13s, d42s, PC4, PC3, PC2, PC1, PC0, u, h1);
                float v = u * h1;
                float4 img = __ldg(row + yc);
                acc[0] += u; acc[1] += v;
                acc[2] = fmaf(img.x, u, acc[2]); acc[3] = fmaf(img.x, v, acc[3]);
                acc[4] = fmaf(img.y, u, acc[4]); acc[5] = fmaf(img.y, v, acc[5]);
                acc[6] = fmaf(img.z, u, acc[6]); acc[7] = fmaf(img.z, v, acc[7]);
                acc[8] = fmaf(u, u, acc[8]); acc[9] = fmaf(v, v, acc[9]);
                acc[10] = fmaf(u, v, acc[10]);
            }
        }

        // exchange halves (double-buffered by step parity -> one barrier/step)
        int par = ip & 1;
        #pragma unroll
        for (int s = 0; s < 11; s++) sAcc[par][wid][s][lane] = acc[s];
        __syncthreads();
        #pragma unroll
        for (int s = 0; s < 11; s++) acc[s] += sAcc[par][wid ^ 1][s][lane];

        // convert (u,v) sums to w-basis quantities (exact identities)
        float U = acc[0], V = acc[1];
        float Uu = acc[8], Vv = acc[9], Uv = acc[10];
        float sw0 = 64.0f - U;
        float sw1 = U - V;
        float sw2 = V;
        float G00 = 64.0f - 2.0f*U + Uu;
        float G11 = Uu - 2.0f*Uv + Vv;
        float G01 = U - V - Uu + Uv;
        float G02 = V - Uv;
        float G12 = Uv - Vv;
        float G22 = Vv;
        float i0 = frcp(sw0 + 1e-10f);
        float i1 = frcp(sw1 + 1e-10f);
        float i2 = frcp(sw2 + 1e-10f);
        float Sc[3]  = {S.x, S.y, S.z};
        float Xu[3] = {acc[2], acc[4], acc[6]};
        float Xv[3] = {acc[3], acc[5], acc[7]};
        float score = 0.0f;
        #pragma unroll
        for (int c = 0; c < 3; c++) {
            float n0 = Sc[c] - Xu[c];
            float n1 = Xu[c] - Xv[c];
            float n2 = Xv[c];
            float c0 = n0*i0, c1 = n1*i1, c2 = n2*i2;
            float quad = c0*c0*G00 + c1*c1*G11 + c2*c2*G22
                       + 2.0f*(c0*c1*G01 + c0*c2*G02 + c1*c2*G12);
            score += quad - 2.0f*(c0*n0 + c1*n1 + c2*n2);
        }

        // butterfly argmin: every lane gets global best (lowest q on ties)
        float bl = score; int bq = q;
        #pragma unroll
        for (int off = 16; off > 0; off >>= 1) {
            float ol = __shfl_xor_sync(0xffffffffu, bl, off);
            int   oq = __shfl_xor_sync(0xffffffffu, bq, off);
            if (ol < bl || (ol == bl && oq < bq)) { bl = ol; bq = oq; }
        }
        p[ip] += cand_range(ip, bq);
    }

    // ---------- finalize: thread = pixel ----------
    Cand K = make_cand(p);
    float dy = (-1.0f + (float)fxr * (2.0f/7.0f)) - K.y0;
    float cc = -1.0f + (float)fyc * (2.0f/7.0f);
    float T1 = fmaf(K.A1y, dy, K.C1);
    float T3 = fmaf(K.A3y, dy, K.C3);
    float T4 = fmaf(K.A4y, dy, K.C4);
    float T2 = fmaf(K.A2y, dy, K.C2);
    float l1 = fmaf(K.A1x, cc, T1);
    float l3 = fmaf(K.A3x, cc, T3);
    float l4 = fmaf(K.A4x, cc, T4);
    float l2 = fmaf(K.A2x, cc, T2);
    float m13 = K.min13 ? fminf(l1, l3) : fmaxf(l1, l3);
    float m42 = K.min42 ? fminf(l4, l2) : fmaxf(l4, l2);
    float d13s = m13 + K.off13s;
    float d42s = m42 + K.off42s;
    float u, h1v;
    fast_hs2(d13s, d42s, PC4, PC3, PC2, PC1, PC0, u, h1v);
    float v = u * h1v;
    float w0 = 1.0f - u, w1 = u - v, w2 = v;
    float4 img = __ldg(tile + fxr * WW + fyc);

    float red[8] = {u, v, img.x*u, img.x*v, img.y*u, img.y*v, img.z*u, img.z*v};
    #pragma unroll
    for (int s = 0; s < 8; s++) {
        #pragma unroll
        for (int off = 16; off > 0; off >>= 1)
            red[s] += __shfl_down_sync(0xffffffffu, red[s], off);
    }
    if (lane == 0) {
        #pragma unroll
        for (int s = 0; s < 8; s++) sRed[wid][s] = red[s];
    }
    __syncthreads();
    float tot[8];
    #pragma unroll
    for (int s = 0; s < 8; s++) tot[s] = sRed[0][s] + sRed[1][s];

    float U = tot[0], V = tot[1];
    float sw0 = 64.0f - U, sw1 = U - V, sw2 = V;
    float i0 = frcp(sw0 + 1e-10f);
    float i1 = frcp(sw1 + 1e-10f);
    float i2 = frcp(sw2 + 1e-10f);
    float Sc[3] = {S.x, S.y, S.z};

    int opix = (fxr + hp) * WW + (fyc + wpx);
    #pragma unroll
    for (int c = 0; c < 3; c++) {
        float Xu = tot[2 + 2*c], Xv = tot[3 + 2*c];
        float c0 = (Sc[c] - Xu) * i0;
        float c1 = (Xu - Xv) * i1;
        float c2 = Xv * i2;
        float pv = w0*c0 + w1*c1 + w2*c2;
        atomicAdd(&g_smoothed[(b*3 + c) * NPIX + opix], pv);
    }
    float d1 = d13s, d2 = d42s;
    float mad = (d1 < 0.0f) ? -d1
              : ((d2 < 0.0f) ? fminf(d1, -d2) : fminf(d1, d2));
    float r = mad * 0.2f;   // scaled dists: mad' = 100*mad
    float lb = 1.0f / (1.0f + r * r);
    atomicAdd(&g_gb[b * NPIX + opix], lb);
}

// Fused post-processing: fold-normalize, 1x1 convs, BN stats (block reduce),
// BN+silu, output. Single block of 1024 threads, 8 elements each.
__global__ void __launch_bounds__(1024) k_postout(
    float* __restrict__ out,
    const float* __restrict__ fbw, const float* __restrict__ fiw,
    const float* __restrict__ fbg, const float* __restrict__ fbb,
    const float* __restrict__ fig, const float* __restrict__ fib
) {
    int tid = threadIdx.x;
    float ybv[8], yiv[8];
    float sb = 0.f, sb2 = 0.f, si = 0.f, si2 = 0.f;
    float fb0 = fbw[0] + fbw[1] + fbw[2];
    float fi0 = fiw[0], fi1 = fiw[1], fi2 = fiw[2];

    #pragma unroll
    for (int j = 0; j < 8; j++) {
        int t = j * 1024 + tid;            // 0..8191
        int b = t >> 12, pix = t & (NPIX - 1);
        int h = pix >> 6, w = pix & 63;
        int ch = min(min(h + 1, HH - h), PSZ);
        int cw = min(min(w + 1, WW - w), PSZ);
        float inv = 1.0f / (float)(ch * cw);

        float sm0 = g_smoothed[(b*3 + 0) * NPIX + pix] * inv;
        float sm1 = g_smoothed[(b*3 + 1) * NPIX + pix] * inv;
        float sm2 = g_smoothed[(b*3 + 2) * NPIX + pix] * inv;
        float yi = sm0 * fi0 + sm1 * fi1 + sm2 * fi2;
        float yb = g_gb[t] * inv * fb0;
        ybv[j] = yb; yiv[j] = yi;
        sb += yb; sb2 += yb * yb;
        si += yi; si2 += yi * yi;
    }

    // block reduction of 4 sums: warp shfl -> smem (32 warps) -> warp 0
    __shared__ float red[4][32];
    __shared__ float totals[4];
    int wid = tid >> 5, lane = tid & 31;
    float vals[4] = {sb, sb2, si, si2};
    #pragma unroll
    for (int s = 0; s < 4; s++) {
        float v = vals[s];
        #pragma unroll
        for (int off = 16; off > 0; off >>= 1)
            v += __shfl_down_sync(0xffffffffu, v, off);
        if (lane == 0) red[s][wid] = v;
    }
    __syncthreads();
    if (wid == 0) {
        #pragma unroll
        for (int s = 0; s < 4; s++) {
            float v = red[s][lane];
            #pragma unroll
            for (int off = 16; off > 0; off >>= 1)
                v += __shfl_down_sync(0xffffffffu, v, off);
            if (lane == 0) totals[s] = v;
        }
    }
    __syncthreads();

    float mb = totals[0] * (1.0f / NSTAT);
    float vb = totals[1] * (1.0f / NSTAT) - mb * mb;
    float rsb = rsqrtf(vb + 1e-5f);
    float mi = totals[2] * (1.0f / NSTAT);
    float vi = totals[3] * (1.0f / NSTAT) - mi * mi;
    float rsi = rsqrtf(vi + 1e-5f);
    float gB = fbg[0], bB = fbb[0], gI = fig[0], bI = fib[0];

    #pragma unroll
    for (int j = 0; j < 8; j++) {
        int t = j * 1024 + tid;
        float nb = gB * (ybv[j] - mb) * rsb + bB;
        out[t] = silu(nb);
        float ni = gI * (yiv[j] - mi) * rsi + bI;
        out[NBATCH * NPIX + t] = silu(ni);
    }
}

// ---------------- launch ----------------
extern "C" void kernel_launch(void* const* d_in, const int* in_sizes, int n_in,
                              void* d_out, int out_size) {
    const float* x   = (const float*)d_in[0];
    const float* rw  = (const float*)d_in[1];
    const float* rg  = (const float*)d_in[2];
    const float* rb  = (const float*)d_in[3];
    const float* fbw = (const float*)d_in[4];
    const float* fbg = (const float*)d_in[5];
    const float* fbb = (const float*)d_in[6];
    const float* fiw = (const float*)d_in[7];
    const float* fig = (const float*)d_in[8];
    const float* fib = (const float*)d_in[9];
    float* out = (float*)d_out;

    k_conv<<<NBATCH * 3 * 16, 256>>>(x, rw);
    k_bnsilu<<<32, 256>>>(rg, rb);
    k_opt<<<NPTOT, 64>>>();
    k_postout<<<1, 1024>>>(out, fbw, fiw, fbg, fbb, fig, fib);
}

// round 14
// speedup vs baseline: 1.0640x; 1.0640x over previous
#include <cuda_runtime.h>
#include <math.h>

#define TWO_PI_F 6.28318530717958647692f
#define PI_F     3.14159265358979323846f
#define INV_PI_F 0.31830988618367094f

#define PSZ   8
#define HH    64
#define WW    64
#define HPN   57
#define NPP   (HPN*HPN)        // 3249
#define NBATCH 2
#define NPTOT (NBATCH*NPP)     // 6498
#define NV    31
#define CINN  32
#define NPIX  (HH*WW)          // 4096
#define NSTAT 8192

// ---------------- device scratch ----------------
__device__ float  g_y[NBATCH*3*NPIX];
__device__ float4 g_xr4[NBATCH*NPIX];
__device__ float  g_smoothed[NBATCH*3*NPIX];
__device__ float  g_gb[NBATCH*NPIX];
__device__ float  g_yb[NBATCH*NPIX];
__device__ float  g_yi[NBATCH*NPIX];
__device__ float  g_stats[16];
__device__ float2 g_cpart[NBATCH*3*16];

// ---------------- packed f32x2 helpers ----------------
typedef unsigned long long f2;
__device__ __forceinline__ f2 pk(float lo, float hi) {
    f2 r; asm("mov.b64 %0,{%1,%2};" : "=l"(r) : "f"(lo), "f"(hi)); return r;
}
__device__ __forceinline__ f2 pk2(float c) { return pk(c, c); }
__device__ __forceinline__ void upk(f2 v, float& lo, float& hi) {
    asm("mov.b64 {%0,%1},%2;" : "=f"(lo), "=f"(hi) : "l"(v));
}
__device__ __forceinline__ f2 fma2(f2 a, f2 b, f2 c) {
    f2 r; asm("fma.rn.f32x2 %0,%1,%2,%3;" : "=l"(r) : "l"(a), "l"(b), "l"(c)); return r;
}
__device__ __forceinline__ f2 mul2(f2 a, f2 b) {
    f2 r; asm("mul.rn.f32x2 %0,%1,%2;" : "=l"(r) : "l"(a), "l"(b)); return r;
}

// ---------------- helpers ----------------
__device__ __forceinline__ float wrap2pi(float v) {
    v = (v >= TWO_PI_F) ? v - TWO_PI_F : v;
    v = (v < 0.0f) ? v + TWO_PI_F : v;
    return v;
}
__device__ __forceinline__ float pow35(float u) {
    float u2 = u*u, u4 = u2*u2, u8 = u4*u4, u16 = u8*u8;
    return u16*u16*u2*u;
}
__device__ __forceinline__ float silu(float v) {
    return v / (1.0f + expf(-v));
}

// Paired h = 0.5 + atan(x)/pi (x pre-scaled by 1/eta=100).
// Proven R12 version (deg-9, 1/pi folded); err(h) ~ 3e-6.
__device__ __forceinline__ void fast_hs2(float xa, float xb,
                                         f2 C4, f2 C3, f2 C2, f2 C1, f2 C0,
                                         float& ha, float& hb) {
    float ia, ib;
    asm("rcp.approx.f32 %0, %1;" : "=f"(ia) : "f"(xa));
    asm("rcp.approx.f32 %0, %1;" : "=f"(ib) : "f"(xb));
    bool ba = fabsf(xa) > 1.0f;
    bool bb = fabsf(xb) > 1.0f;
    float ta = ba ? ia : xa;
    float tb = bb ? ib : xb;
    f2 t = pk(ta, tb);
    f2 s = mul2(t, t);
    f2 p = fma2(C4, s, C3);
    p = fma2(p, s, C2);
    p = fma2(p, s, C1);
    p = fma2(p, s, C0);
    f2 r0 = mul2(t, p);
    float ra, rb; upk(r0, ra, rb);
    float fa = ba ? (copysignf(0.5f, xa) - ra) : ra;
    float fb = bb ? (copysignf(0.5f, xb) - rb) : rb;
    ha = fa + 0.5f;
    hb = fb + 0.5f;
}

// Angle-derived candidate part (independent of x0, y0).
// Sign-free line coefficients; sg handled by predicate min/max.
struct Ang {
    float A1x,A1y,A3x,A3y,A4x,A4y,A2x,A2y;
    float off13s, off42s;
    bool  min13, min42;
};

__device__ __forceinline__ Ang make_ang(float e0, float e1, float e2) {
    Ang A;
    float m0 = wrap2pi(e0), m1 = wrap2pi(e1), m2 = wrap2pi(e2);
    float lo = fminf(m0, m1), hi = fmaxf(m0, m1);
    float a1 = fminf(lo, m2);
    float a3 = fmaxf(hi, m2);
    float a2 = fmaxf(lo, fminf(hi, m2));
    float a4 = 0.5f*(a1 + a3) + ((a3 > a1) ? PI_F : 0.0f);
    float d13 = a3 - a1;
    float m   = a2 - a4;
    float d42 = (m < 0.0f) ? m + TWO_PI_F : m;
    A.min13 = (d13 < PI_F);
    A.min42 = (d42 < PI_F);
    A.off13s = 10.0f * pow35(d13 * INV_PI_F - 1.0f);
    A.off42s = 10.0f * pow35(d42 * INV_PI_F - 1.0f);
    float s1,c1,s2,c2,s3,c3,s4,c4;
    __sincosf(a1, &s1, &c1);
    __sincosf(a2, &s2, &c2);
    __sincosf(a3, &s3, &c3);
    __sincosf(a4, &s4, &c4);
    const float f = 100.0f;
    A.A1x = -f * s1;  A.A1y =  f * c1;
    A.A3x =  f * s3;  A.A3y = -f * c3;
    A.A4x = -f * s4;  A.A4y =  f * c4;
    A.A2x =  f * s2;  A.A2y = -f * c2;
    return A;
}

__device__ __forceinline__ float cand_range(int ip, int q) {
    return (ip < 3) ? (float)q * (TWO_PI_F / 31.0f)
                    : (-3.0f + (float)q * 0.2f);
}

// ---------------- kernels ----------------
__global__ void k_conv(const float* __restrict__ x, const float* __restrict__ rw) {
    int gt = blockIdx.x * 256 + threadIdx.x;   // 0..24575
    g_smoothed[gt] = 0.0f;
    if (gt < NBATCH*NPIX) g_gb[gt] = 0.0f;
    if (gt < 16) g_stats[gt] = 0.0f;

    int bo = blockIdx.x >> 4;
    int chunk = blockIdx.x & 15;
    int b = bo / 3, o = bo % 3;
    int pix = chunk * 256 + threadIdx.x;
    const float* xp = x + (size_t)b * CINN * NPIX + pix;
    float acc = 0.0f;
    #pragma unroll
    for (int c = 0; c < CINN; c++)
        acc = fmaf(xp[c * NPIX], rw[o * CINN + c], acc);
    g_y[(b*3 + o) * NPIX + pix] = acc;

    __shared__ float s1[256], s2[256];
    s1[threadIdx.x] = acc; s2[threadIdx.x] = acc * acc;
    __syncthreads();
    for (int s = 128; s > 0; s >>= 1) {
        if (threadIdx.x < s) { s1[threadIdx.x] += s1[threadIdx.x+s]; s2[threadIdx.x] += s2[threadIdx.x+s]; }
        __syncthreads();
    }
    if (threadIdx.x == 0) g_cpart[blockIdx.x] = make_float2(s1[0], s2[0]);
}

__global__ void k_bnsilu(const float* __restrict__ gamma, const float* __restrict__ beta) {
    int t = blockIdx.x * 256 + threadIdx.x;
    int b = t >> 12, pix = t & (NPIX - 1);
    float v[3];
    #pragma unroll
    for (int c = 0; c < 3; c++) {
        float s = 0.0f, ss = 0.0f;
        #pragma unroll
        for (int b2 = 0; b2 < NBATCH; b2++)
            #pragma unroll
            for (int ch = 0; ch < 16; ch++) {
                float2 pv = g_cpart[(b2*3 + c) * 16 + ch];
                s += pv.x; ss += pv.y;
            }
        float m   = s  * (1.0f / NSTAT);
        float var = ss * (1.0f / NSTAT) - m * m;
        float y   = g_y[(b*3 + c) * NPIX + pix];
        float n   = gamma[c] * (y - m) * rsqrtf(var + 1e-5f) + beta[c];
        v[c] = silu(n);
    }
    g_xr4[t] = make_float4(v[0], v[1], v[2], 0.0f);
}

// Fused: per-patch channel sums + 5-step coordinate descent + finalize.
__global__ void __launch_bounds__(64, 16) k_opt() {
    int tid  = threadIdx.x;
    int wid  = tid >> 5;
    int lane = tid & 31;
    int P = blockIdx.x;
    int b = P / NPP, pp = P - b * NPP;
    int hp = pp / HPN, wpx = pp - hp * HPN;
    const float4* tile = g_xr4 + b * NPIX + hp * WW + wpx;

    __shared__ float sAcc[2][2][11][32];  // [parity][warp][acc][lane]
    __shared__ float sRed[2][8];

    const f2 PC4 = pk2( 0.00663216f);
    const f2 PC3 = pk2(-0.02709664f);
    const f2 PC2 = pk2( 0.05733850f);
    const f2 PC1 = pk2(-0.10513345f);
    const f2 PC0 = pk2( 0.31826723f);

    // ---------- prologue: per-patch channel sums (thread = pixel) ----------
    int fxr = tid >> 3, fyc = tid & 7;
    {
        float4 fimg = __ldg(tile + fxr * WW + fyc);
        float t0 = fimg.x, t1 = fimg.y, t2 = fimg.z;
        #pragma unroll
        for (int off = 16; off > 0; off >>= 1) {
            t0 += __shfl_down_sync(0xffffffffu, t0, off);
            t1 += __shfl_down_sync(0xffffffffu, t1, off);
            t2 += __shfl_down_sync(0xffffffffu, t2, off);
        }
        if (lane == 0) { sRed[wid][0] = t0; sRed[wid][1] = t1; sRed[wid][2] = t2; }
    }
    __syncthreads();
    float4 S = make_float4(sRed[0][0] + sRed[1][0],
                           sRed[0][1] + sRed[1][1],
                           sRed[0][2] + sRed[1][2], 0.0f);

    float p[5] = {0.f, 0.f, 0.f, 0.f, 0.f};
    int q = (lane < NV) ? lane : (NV - 1);
    Ang A;

    #pragma unroll 1
    for (int ip = 0; ip < 5; ip++) {
        float x0, y0;
        if (ip < 3) {
            float e0 = p[0], e1 = p[1], e2 = p[2];
            float dq = cand_range(ip, q);
            if (ip == 0) e0 += dq; else if (ip == 1) e1 += dq; else e2 += dq;
            A = make_ang(e0, e1, e2);
            x0 = p[3]; y0 = p[4];
        } else {
            if (ip == 3) A = make_ang(p[0], p[1], p[2]);  // angles now fixed
            x0 = (ip == 3) ? p[3] + cand_range(3, q) : p[3];
            y0 = (ip == 4) ? p[4] + cand_range(4, q) : p[4];
        }
        // offsets folded into C: d = minmax(l1+off, l3+off) == minmax+off exact
        float nx0 = -x0;
        float C1 = fmaf(A.A1x, nx0, A.off13s);
        float C3 = fmaf(A.A3x, nx0, A.off13s);
        float C4 = fmaf(A.A4x, nx0, A.off42s);
        float C2 = fmaf(A.A2x, nx0, A.off42s);

        float acc[11];
        #pragma unroll
        for (int s = 0; s < 11; s++) acc[s] = 0.0f;

        int rbase = wid * 4;
        #pragma unroll 1
        for (int xr = 0; xr < 4; xr++) {
            int row_i = rbase + xr;
            float dy = (-1.0f + (float)row_i * (2.0f/7.0f)) - y0;
            float T1 = fmaf(A.A1y, dy, C1);
            float T3 = fmaf(A.A3y, dy, C3);
            float T4 = fmaf(A.A4y, dy, C4);
            float T2 = fmaf(A.A2y, dy, C2);
            const float4* row = tile + row_i * WW;
            #pragma unroll
            for (int yc = 0; yc < PSZ; yc++) {
                float cc = -1.0f + (float)yc * (2.0f/7.0f);
                float l1 = fmaf(A.A1x, cc, T1);
                float l3 = fmaf(A.A3x, cc, T3);
                float l4 = fmaf(A.A4x, cc, T4);
                float l2 = fmaf(A.A2x, cc, T2);
                float d13s = A.min13 ? fminf(l1, l3) : fmaxf(l1, l3);
                float d42s = A.min42 ? fminf(l4, l2) : fmaxf(l4, l2);
                float u, h1;
                fast_hs2(d13s, d42s, PC4, PC3, PC2, PC1, PC0, u, h1);
                float v = u * h1;
                float4 img = __ldg(row + yc);
                acc[0] += u; acc[1] += v;
                acc[2] = fmaf(img.x, u, acc[2]); acc[3] = fmaf(img.x, v, acc[3]);
                acc[4] = fmaf(img.y, u, acc[4]); acc[5] = fmaf(img.y, v, acc[5]);
                acc[6] = fmaf(img.z, u, acc[6]); acc[7] = fmaf(img.z, v, acc[7]);
                acc[8] = fmaf(u, u, acc[8]); acc[9] = fmaf(v, v, acc[9]);
                acc[10] = fmaf(u, v, acc[10]);
            }
        }

        // exchange halves (double-buffered by step parity -> one barrier/step)
        int par = ip & 1;
        #pragma unroll
        for (int s = 0; s < 11; s++) sAcc[par][wid][s][lane] = acc[s];
        __syncthreads();
        #pragma unroll
        for (int s = 0; s < 11; s++) acc[s] += sAcc[par][wid ^ 1][s][lane];

        // convert (u,v) sums to w-basis quantities (exact identities)
        float U = acc[0], V = acc[1];
        float Uu = acc[8], Vv = acc[9], Uv = acc[10];
        float sw0 = 64.0f - U;
        float sw1 = U - V;
        float sw2 = V;
        float G00 = 64.0f - 2.0f*U + Uu;
        float G11 = Uu - 2.0f*Uv + Vv;
        float G01 = U - V - Uu + Uv;
        float G02 = V - Uv;
        float G12 = Uv - Vv;
        float G22 = Vv;
        float i0 = 1.0f / (sw0 + 1e-10f);
        float i1 = 1.0f / (sw1 + 1e-10f);
        float i2 = 1.0f / (sw2 + 1e-10f);
        float Sc[3]  = {S.x, S.y, S.z};
        float Xu[3] = {acc[2], acc[4], acc[6]};
        float Xv[3] = {acc[3], acc[5], acc[7]};
        float score = 0.0f;
        #pragma unroll
        for (int c = 0; c < 3; c++) {
            float n0 = Sc[c] - Xu[c];
            float n1 = Xu[c] - Xv[c];
            float n2 = Xv[c];
            float c0 = n0*i0, c1 = n1*i1, c2 = n2*i2;
            float quad = c0*c0*G00 + c1*c1*G11 + c2*c2*G22
                       + 2.0f*(c0*c1*G01 + c0*c2*G02 + c1*c2*G12);
            score += quad - 2.0f*(c0*n0 + c1*n1 + c2*n2);
        }

        // butterfly argmin: every lane gets global best (lowest q on ties)
        float bl = score; int bq = q;
        #pragma unroll
        for (int off = 16; off > 0; off >>= 1) {
            float ol = __shfl_xor_sync(0xffffffffu, bl, off);
            int   oq = __shfl_xor_sync(0xffffffffu, bq, off);
            if (ol < bl || (ol == bl && oq < bq)) { bl = ol; bq = oq; }
        }
        p[ip] += cand_range(ip, bq);
    }

    // ---------- finalize: thread = pixel (A still valid from step 4) ----------
    float x0 = p[3], y0 = p[4];
    float nx0 = -x0;
    float C1 = fmaf(A.A1x, nx0, A.off13s);
    float C3 = fmaf(A.A3x, nx0, A.off13s);
    float C4 = fmaf(A.A4x, nx0, A.off42s);
    float C2 = fmaf(A.A2x, nx0, A.off42s);
    float dy = (-1.0f + (float)fxr * (2.0f/7.0f)) - y0;
    float cc = -1.0f + (float)fyc * (2.0f/7.0f);
    float T1 = fmaf(A.A1y, dy, C1);
    float T3 = fmaf(A.A3y, dy, C3);
    float T4 = fmaf(A.A4y, dy, C4);
    float T2 = fmaf(A.A2y, dy, C2);
    float l1 = fmaf(A.A1x, cc, T1);
    float l3 = fmaf(A.A3x, cc, T3);
    float l4 = fmaf(A.A4x, cc, T4);
    float l2 = fmaf(A.A2x, cc, T2);
    float d13s = A.min13 ? fminf(l1, l3) : fmaxf(l1, l3);
    float d42s = A.min42 ? fminf(l4, l2) : fmaxf(l4, l2);
    float u, h1v;
    fast_hs2(d13s, d42s, PC4, PC3, PC2, PC1, PC0, u, h1v);
    float v = u * h1v;
    float w0 = 1.0f - u, w1 = u - v, w2 = v;
    float4 img = __ldg(tile + fxr * WW + fyc);

    float red[8] = {u, v, img.x*u, img.x*v, img.y*u, img.y*v, img.z*u, img.z*v};
    #pragma unroll
    for (int s = 0; s < 8; s++) {
        #pragma unroll
        for (int off = 16; off > 0; off >>= 1)
            red[s] += __shfl_down_sync(0xffffffffu, red[s], off);
    }
    if (lane == 0) {
        #pragma unroll
        for (int s = 0; s < 8; s++) sRed[wid][s] = red[s];
    }
    __syncthreads();
    float tot[8];
    #pragma unroll
    for (int s = 0; s < 8; s++) tot[s] = sRed[0][s] + sRed[1][s];

    float U = tot[0], V = tot[1];
    float sw0 = 64.0f - U, sw1 = U - V, sw2 = V;
    float i0 = 1.0f / (sw0 + 1e-10f);
    float i1 = 1.0f / (sw1 + 1e-10f);
    float i2 = 1.0f / (sw2 + 1e-10f);
    float Sc[3] = {S.x, S.y, S.z};

    int opix = (fxr + hp) * WW + (fyc + wpx);
    #pragma unroll
    for (int c = 0; c < 3; c++) {
        float Xu = tot[2 + 2*c], Xv = tot[3 + 2*c];
        float c0 = (Sc[c] - Xu) * i0;
        float c1 = (Xu - Xv) * i1;
        float c2 = Xv * i2;
        float pv = w0*c0 + w1*c1 + w2*c2;
        atomicAdd(&g_smoothed[(b*3 + c) * NPIX + opix], pv);
    }
    float d1 = d13s, d2 = d42s;
    float mad = (d1 < 0.0f) ? -d1
              : ((d2 < 0.0f) ? fminf(d1, -d2) : fminf(d1, d2));
    float r = mad * 0.2f;   // scaled dists: mad' = 100*mad
    float lb = 1.0f / (1.0f + r * r);
    atomicAdd(&g_gb[b * NPIX + opix], lb);
}

__global__ void k_post1(const float* __restrict__ fbw, const float* __restrict__ fiw) {
    int t = blockIdx.x * 256 + threadIdx.x;
    int b = t >> 12, pix = t & (NPIX - 1);
    int h = pix >> 6, w = pix & 63;
    int ch = min(min(h + 1, HH - h), PSZ);
    int cw = min(min(w + 1, WW - w), PSZ);
    float inv = 1.0f / (float)(ch * cw);

    float sm0 = g_smoothed[(b*3 + 0) * NPIX + pix] * inv;
    float sm1 = g_smoothed[(b*3 + 1) * NPIX + pix] * inv;
    float sm2 = g_smoothed[(b*3 + 2) * NPIX + pix] * inv;
    float yi = sm0 * fiw[0] + sm1 * fiw[1] + sm2 * fiw[2];
    float gbv = g_gb[t] * inv;
    float yb = gbv * (fbw[0] + fbw[1] + fbw[2]);
    g_yi[t] = yi;
    g_yb[t] = yb;

    // shfl-based block reduction of 4 sums (2 barriers total)
    __shared__ float red[4][8];
    int wid = threadIdx.x >> 5, lane = threadIdx.x & 31;
    float vals[4] = {yb, yb*yb, yi, yi*yi};
    #pragma unroll
    for (int s = 0; s < 4; s++) {
        float v = vals[s];
        #pragma unroll
        for (int off = 16; off > 0; off >>= 1)
            v += __shfl_down_sync(0xffffffffu, v, off);
        if (lane == 0) red[s][wid] = v;
    }
    __syncthreads();
    if (wid == 0 && lane < 8) {
        #pragma unroll
        for (int s = 0; s < 4; s++) {
            float v = red[s][lane];
            #pragma unroll
            for (int off = 4; off > 0; off >>= 1)
                v += __shfl_down_sync(0xffu, v, off, 8);
            if (lane == 0) atomicAdd(&g_stats[6 + s], v);
        }
    }
}

__global__ void k_out(float* __restrict__ out,
                      const float* __restrict__ fbg, const float* __restrict__ fbb,
                      const float* __restrict__ fig, const float* __restrict__ fib) {
    int t = blockIdx.x * 256 + threadIdx.x;
    float mb = g_stats[6] * (1.0f / NSTAT);
    float vb = g_stats[7] * (1.0f / NSTAT) - mb * mb;
    float nb = fbg[0] * (g_yb[t] - mb) * rsqrtf(vb + 1e-5f) + fbb[0];
    out[t] = silu(nb);

    float mi = g_stats[8] * (1.0f / NSTAT);
    float vi = g_stats[9] * (1.0f / NSTAT) - mi * mi;
    float ni = fig[0] * (g_yi[t] - mi) * rsqrtf(vi + 1e-5f) + fib[0];
    out[NBATCH * NPIX + t] = silu(ni);
}

// ---------------- launch ----------------
extern "C" void kernel_launch(void* const* d_in, const int* in_sizes, int n_in,
                              void* d_out, int out_size) {
    const float* x   = (const float*)d_in[0];
    const float* rw  = (const float*)d_in[1];
    const float* rg  = (const float*)d_in[2];
    const float* rb  = (const float*)d_in[3];
    const float* fbw = (const float*)d_in[4];
    const float* fbg = (const float*)d_in[5];
    const float* fbb = (const float*)d_in[6];
    const float* fiw = (const float*)d_in[7];
    const float* fig = (const float*)d_in[8];
    const float* fib = (const float*)d_in[9];
    float* out = (float*)d_out;

    k_conv<<<NBATCH * 3 * 16, 256>>>(x, rw);
    k_bnsilu<<<32, 256>>>(rg, rb);
    k_opt<<<NPTOT, 64>>>();
    k_post1<<<32, 256>>>(fbw, fiw);
    k_out<<<32, 256>>>(out, fbg, fbb, fig, fib);
}